// round 15
// baseline (speedup 1.0000x reference)
#include <cuda_runtime.h>
#include <math.h>

// Problem constants (fixed shapes)
#define DN 32
#define HN 192
#define WN 192
#define DHW (DN*HN*WN)      // 1179648
#define BN 4
#define CN 7
#define NID 16
#define NBI (BN*NID)        // 64
#define NB 4096             // histogram bins over e in [0,2]
#define SLICES 37
#define CH ((DHW + SLICES - 1) / SLICES)   // 31884  (< 65535: u16 bin-counts safe)
#define NPAIR (NID/2)       // 8 id-pairs per batch

typedef unsigned long long ull;

// ---------------- device scratch (static; zero-initialized at load;
// every kernel restores its accumulators to zero after consuming them,
// so each graph replay starts from a clean state) ----------------
__device__ float4 g_se[(size_t)BN*DHW];             // tanh(pred[:3])+xyzm, seed(+id in low mantissa)
__device__ unsigned g_hcnt[NBI][2*NB];              // merged count histograms (2MB)
__device__ double g_acc[NBI][10];                   // cnt, sum_xyz, sum(sig+16), sum sig^2
__device__ double g_bg[BN];
__device__ double g_seedl[BN];
__device__ double g_instl[BN];
__device__ float  g_center[NBI][3];
__device__ float  g_sexp[NBI][3];
__device__ float  g_cnt[NBI];
__device__ float  g_varsum[BN];
__device__ float  g_denom[BN];

// HW tanh (MUFU.TANH, sm_75+); feeds only the binned-distance path
__device__ __forceinline__ float htanh(float x) {
    float y;
    asm("tanh.approx.f32 %0, %1;" : "=f"(y) : "f"(x));
    return y;
}

// ---------------- pass 1: preprocess + per-instance accumulators ----------------
// 3 packed u64 words per fg voxel, merged across the 4-voxel quad by id before
// hitting per-HALF-WARP replica banks (16 replicas: halves intra-replica
// same-address conflict degree vs per-warp replicas):
//  w0: cnt[0:10) | zi[10:24) | yi[24:41) | xi[41:58)          (exact integers)
//  w1: (s0+16)*128 [0:21) | (s1+16)*128 [21:42) | (s2+16)*128 [42:63)
//  w2: s0^2*32 [0:21)     | s1^2*32 [21:42)     | s2^2*32 [42:63)
#define VOXN(i, p0,p1,p2,s0,s1,s2,p6, lbv, xmv, xiv, vi)                         \
    {                                                                            \
        float e0 = htanh(p0) + (xmv);                                            \
        float e1 = htanh(p1) + ym;                                               \
        float e2 = htanh(p2) + zm;                                               \
        float seed = __fdividef(1.f, 1.f + __expf(-(p6)));                       \
        unsigned wb = (__float_as_uint(seed) & ~31u) | (unsigned)ids[i];         \
        o4[vi] = make_float4(e0, e1, e2, __uint_as_float(wb));                   \
        W0[i] = 1ULL | ((ull)zi << 10) | ((ull)yi << 24) | ((ull)(xiv) << 41);   \
        W1[i] = (ull)__float2uint_rn(fmaf(s0,128.f,2048.f))                      \
              | ((ull)__float2uint_rn(fmaf(s1,128.f,2048.f)) << 21)              \
              | ((ull)__float2uint_rn(fmaf(s2,128.f,2048.f)) << 42);             \
        W2[i] = (ull)__float2uint_rn((s0)*(s0)*32.f)                             \
              | ((ull)__float2uint_rn((s1)*(s1)*32.f) << 21)                     \
              | ((ull)__float2uint_rn((s2)*(s2)*32.f) << 42);                    \
        if ((lbv) == 0) bgl += seed * seed;                                      \
    }

__global__ void __launch_bounds__(256) k1(const float* __restrict__ pred,
                                          const int* __restrict__ inst,
                                          const int* __restrict__ lab) {
    __shared__ ull sacc[16][NID*3];   // one replica per half-warp (6KB)
    __shared__ float swr[8];
    int tid = threadIdx.x;
    for (int i = tid; i < 16*NID*3; i += 256) (&sacc[0][0])[i] = 0ULL;
    __syncthreads();
    ull* my = sacc[tid >> 4];   // half-warp replica (tid/16 in 0..15)

    int b = blockIdx.y;
    const float4* __restrict__ p4 = (const float4*)(pred + (size_t)b * CN * DHW);
    const int4*   __restrict__ i4 = (const int4*)(inst + (size_t)b * DHW);
    const int4*   __restrict__ l4 = (const int4*)(lab  + (size_t)b * DHW);
    float4* o4 = g_se + (size_t)b * DHW;
    float bgl = 0.f;
    const int Q = DHW / 4;

    for (int q = blockIdx.x * 256 + tid; q < Q; q += gridDim.x * 256) {
        float4 P0 = p4[q],       P1 = p4[Q+q],   P2 = p4[2*Q+q];
        float4 S0 = p4[3*Q+q],   S1 = p4[4*Q+q], S2 = p4[5*Q+q];
        float4 P6 = p4[6*Q+q];
        int4 ID = i4[q];
        int4 LB = l4[q];
        int v = q * 4;
        int x0 = v % WN;
        int r  = v / WN;
        int yi = r % HN, zi = r / HN;
        float ym = (float)yi * (1.f/(HN-1));
        float zm = (float)zi * (1.f/(DN-1));
        float xm = (float)x0 * (1.f/(WN-1));

        int ids[4] = {ID.x, ID.y, ID.z, ID.w};
        ull W0[4], W1[4], W2[4];
        VOXN(0, P0.x, P1.x, P2.x, S0.x, S1.x, S2.x, P6.x, LB.x, xm,              x0,   v+0)
        VOXN(1, P0.y, P1.y, P2.y, S0.y, S1.y, S2.y, P6.y, LB.y, xm + 1.f/(WN-1), x0+1, v+1)
        VOXN(2, P0.z, P1.z, P2.z, S0.z, S1.z, S2.z, P6.z, LB.z, xm + 2.f/(WN-1), x0+2, v+2)
        VOXN(3, P0.w, P1.w, P2.w, S0.w, S1.w, S2.w, P6.w, LB.w, xm + 3.f/(WN-1), x0+3, v+3)

        // merge same-id voxels within the quad, then one atomic triple per id
        #pragma unroll
        for (int i = 0; i < 4; i++) {
            int idv = ids[i];
            if (idv > 0) {
                ull a0 = W0[i], a1 = W1[i], a2 = W2[i];
                #pragma unroll
                for (int j = i + 1; j < 4; j++) {
                    if (ids[j] == idv) { a0 += W0[j]; a1 += W1[j]; a2 += W2[j]; ids[j] = 0; }
                }
                ull* s = &my[(idv-1)*3];
                atomicAdd(&s[0], a0);
                atomicAdd(&s[1], a1);
                atomicAdd(&s[2], a2);
            }
        }
    }
    // warp-reduce bg
    for (int o = 16; o; o >>= 1) bgl += __shfl_down_sync(0xffffffffu, bgl, o);
    if ((tid & 31) == 0) swr[tid >> 5] = bgl;
    __syncthreads();
    if (tid == 0) {
        double s = 0.0;
        for (int i = 0; i < 8; i++) s += (double)swr[i];
        atomicAdd(&g_bg[b], s);
    }
    // decode fields per replica, sum, merge to global (48 threads: id x word)
    if (tid < NID*3) {
        int id = tid / 3, w = tid % 3;
        double* g = g_acc[b*NID + id];
        if (w == 0) {
            ull cnt = 0, sxi = 0, syi = 0, szi = 0;
            #pragma unroll
            for (int rp = 0; rp < 16; rp++) {
                ull v = sacc[rp][id*3];
                cnt += v & 1023ULL;
                szi += (v >> 10) & 0x3FFFULL;
                syi += (v >> 24) & 0x1FFFFULL;
                sxi += (v >> 41);
            }
            if (cnt) {
                atomicAdd(&g[0], (double)cnt);
                atomicAdd(&g[1], (double)sxi * (1.0/(WN-1)));
                atomicAdd(&g[2], (double)syi * (1.0/(HN-1)));
                atomicAdd(&g[3], (double)szi * (1.0/(DN-1)));
            }
        } else {
            ull f0 = 0, f1 = 0, f2 = 0;
            #pragma unroll
            for (int rp = 0; rp < 16; rp++) {
                ull v = sacc[rp][id*3 + w];
                f0 += v & 0x1FFFFFULL;
                f1 += (v >> 21) & 0x1FFFFFULL;
                f2 += (v >> 42);
            }
            if (f0 | f1 | f2) {
                double sc = (w == 1) ? (1.0/128.0) : (1.0/32.0);
                int base = (w == 1) ? 4 : 7;
                atomicAdd(&g[base+0], (double)f0 * sc);
                atomicAdd(&g[base+1], (double)f1 * sc);
                atomicAdd(&g[base+2], (double)f2 * sc);
            }
        }
    }
}

// ---------------- pass 2: per-instance stats (zeroes g_acc after reading) ----------------
// g_acc[4..6] hold sum(sigma+16): subtract 16*cnt here
__global__ void k2() {
    __shared__ float sobj[BN], svar[BN];
    int t = threadIdx.x;            // 0..63  (b*16 + (id-1))
    if (t < BN) { sobj[t] = 0.f; svar[t] = 0.f; }
    __syncthreads();
    int b = t / NID;

    double a[10];
    #pragma unroll
    for (int i = 0; i < 10; i++) { a[i] = g_acc[t][i]; g_acc[t][i] = 0.0; }

    double cnt = a[0];
    bool ex = cnt > 0.0;
    double safe = cnt > 1.0 ? cnt : 1.0;
    double c0 = a[1] / safe, c1 = a[2] / safe, c2 = a[3] / safe;
    double m0 = (a[4] - 16.0*cnt) / safe;
    double m1 = (a[5] - 16.0*cnt) / safe;
    double m2 = (a[6] - 16.0*cnt) / safe;
    double var = 0.0;
    if (ex) {
        var = ((a[7] - cnt*m0*m0) +
               (a[8] - cnt*m1*m1) +
               (a[9] - cnt*m2*m2)) / (3.0 * safe);
    }
    g_center[t][0] = (float)c0; g_center[t][1] = (float)c1; g_center[t][2] = (float)c2;
    g_sexp[t][0] = expf((float)(m0 * 10.0));
    g_sexp[t][1] = expf((float)(m1 * 10.0));
    g_sexp[t][2] = expf((float)(m2 * 10.0));
    g_cnt[t] = ex ? (float)cnt : 0.f;

    atomicAdd(&sobj[b], ex ? 1.f : 0.f);
    atomicAdd(&svar[b], (float)var);
    __syncthreads();
    if (t < BN) {
        g_denom[t]  = sobj[t] > 1.f ? sobj[t] : 1.f;
        g_varsum[t] = svar[t];
    }
}

// ---------------- pass 3: per-(b,idpair,slice) packed-u16 count histograms + seed loss ----------------
// two adjacent bins share one u32 word: sh[off>>1] += 1 << ((off&1)*16).
// Per-bin count <= CH = 31884 < 65535, no overflow. 32KB smem/CTA -> 4 CTAs/SM.
#define K3_PAIR(S)                                                               \
    {                                                                            \
        unsigned iv = __float_as_uint(S.w) & 31u;                                \
        float dxA = S.x - cA0, dyA = S.y - cA1, dzA = S.z - cA2;                 \
        float d2A = fmaf(dxA*dxA, eA0, fmaf(dyA*dyA, eA1, dzA*dzA*eA2));         \
        float dA = exp2f(fmaf(d2A, -1.44269504089f, 12.f));                      \
        bool gtA = (iv == idA);                                                  \
        int ubA = (int)dA; ubA = ubA > NB-1 ? NB-1 : ubA;                        \
        unsigned offA = gtA ? (unsigned)(2*NB - 1 - ubA) : (unsigned)ubA;        \
        atomicAdd(&shA[offA >> 1], 1u << ((offA & 1u) << 4));                    \
        if (gtA) { float df = S.w - dA * (1.f/4096.f); sacc += df * df; }        \
        float dxB = S.x - cB0, dyB = S.y - cB1, dzB = S.z - cB2;                 \
        float d2B = fmaf(dxB*dxB, eB0, fmaf(dyB*dyB, eB1, dzB*dzB*eB2));         \
        float dB = exp2f(fmaf(d2B, -1.44269504089f, 12.f));                      \
        bool gtB = (iv == idB);                                                  \
        int ubB = (int)dB; ubB = ubB > NB-1 ? NB-1 : ubB;                        \
        unsigned offB = gtB ? (unsigned)(2*NB - 1 - ubB) : (unsigned)ubB;        \
        atomicAdd(&shB[offB >> 1], 1u << ((offB & 1u) << 4));                    \
        if (gtB) { float df = S.w - dB * (1.f/4096.f); sacc += df * df; }        \
    }

__global__ void __launch_bounds__(512, 4) k3() {
    extern __shared__ unsigned sh[];     // 2 x NB u32 words (= 2 x 2*NB u16 bins) = 32KB
    unsigned* shA = sh;
    unsigned* shB = sh + NB;
    __shared__ float swr[16];

    int b = blockIdx.z, p = blockIdx.x, s = blockIdx.y;
    int biA = b * NID + 2*p, biB = biA + 1;
    unsigned idA = 2*p + 1, idB = 2*p + 2;
    if (g_cnt[biA] == 0.f && g_cnt[biB] == 0.f) return;

    float cA0 = g_center[biA][0], cA1 = g_center[biA][1], cA2 = g_center[biA][2];
    float eA0 = g_sexp[biA][0],   eA1 = g_sexp[biA][1],   eA2 = g_sexp[biA][2];
    float cB0 = g_center[biB][0], cB1 = g_center[biB][1], cB2 = g_center[biB][2];
    float eB0 = g_sexp[biB][0],   eB1 = g_sexp[biB][1],   eB2 = g_sexp[biB][2];

    int tid = threadIdx.x;
    for (int i = tid; i < 2*NB; i += 512) sh[i] = 0u;
    __syncthreads();

    const float4* __restrict__ se = g_se + (size_t)b * DHW;
    float sacc = 0.f;
    int v0 = s * CH;
    int vend = v0 + CH; if (vend > DHW) vend = DHW;

    int v = v0 + tid;
    for (; v + 512 < vend; v += 1024) {
        float4 S1 = se[v];
        float4 S2 = se[v + 512];
        K3_PAIR(S1)
        K3_PAIR(S2)
    }
    for (; v < vend; v += 512) {
        float4 S1 = se[v];
        K3_PAIR(S1)
    }

    // warp-reduce seed loss (both instances share batch b)
    for (int o = 16; o; o >>= 1) sacc += __shfl_down_sync(0xffffffffu, sacc, o);
    if ((tid & 31) == 0) swr[tid >> 5] = sacc;
    __syncthreads();
    if (tid == 0) {
        double ssum = 0.0;
        for (int i = 0; i < 16; i++) ssum += (double)swr[i];
        atomicAdd(&g_seedl[b], ssum);
    }
    // unpack + sparse merge into single global histogram (RED, no return; deterministic)
    for (int i = tid; i < NB; i += 512) {
        unsigned wA = shA[i];
        unsigned wB = shB[i];
        if (wA & 0xFFFFu)  atomicAdd(&g_hcnt[biA][2*i],     wA & 0xFFFFu);
        if (wA >> 16)      atomicAdd(&g_hcnt[biA][2*i + 1], wA >> 16);
        if (wB & 0xFFFFu)  atomicAdd(&g_hcnt[biB][2*i],     wB & 0xFFFFu);
        if (wB >> 16)      atomicAdd(&g_hcnt[biB][2*i + 1], wB >> 16);
    }
}

// ---------------- pass 4: Lovasz via histogram scan, all-fp32 (counts exact in fp32),
// shuffle-based scan, zeroes g_hcnt after reading ----------------
#define NT4 512
#define PER4 (NB / NT4)   // 8
__global__ void k4() {
    __shared__ float pc[NB], nc[NB];     // counts by ascending bin
    __shared__ float wps[16], wns[16];   // per-warp scan totals
    __shared__ float sred[16];

    int bi = blockIdx.x, b = bi / NID;
    int t = threadIdx.x;
    int lane = t & 31, w = t >> 5;

    // phase 1: coalesced gather of merged counts + restore zeros for next replay
    #pragma unroll
    for (int i = 0; i < PER4; i++) {
        int j = i * NT4 + t;             // ascending bin index, coalesced
        pc[j] = (float)g_hcnt[bi][NB + j];
        nc[j] = (float)g_hcnt[bi][j];
        g_hcnt[bi][NB + j] = 0u;
        g_hcnt[bi][j] = 0u;
    }
    float G = g_cnt[bi];
    if (G == 0.f) return;
    __syncthreads();

    // phase 2: thread-local sums over descending positions [t*PER4, t*PER4+PER4)
    float tp = 0.f, tn = 0.f;
    #pragma unroll
    for (int i = 0; i < PER4; i++) {
        int j = NB - 1 - (t * PER4 + i);
        tp += pc[j]; tn += nc[j];
    }
    // warp-inclusive scan via shuffles
    float ip = tp, inn = tn;
    #pragma unroll
    for (int o = 1; o < 32; o <<= 1) {
        float up = __shfl_up_sync(0xffffffffu, ip, o);
        float un = __shfl_up_sync(0xffffffffu, inn, o);
        if (lane >= o) { ip += up; inn += un; }
    }
    if (lane == 31) { wps[w] = ip; wns[w] = inn; }
    __syncthreads();
    float offP = 0.f, offN = 0.f;
    #pragma unroll
    for (int k = 0; k < 16; k++) {
        float vp = wps[k], vn = wns[k];
        if (k < w) { offP += vp; offN += vn; }
    }
    float P = offP + ip - tp;   // exclusive prefix (exact: integer-valued floats)
    float N = offN + inn - tn;

    float contrib = 0.f;
    #pragma unroll
    for (int i = 0; i < PER4; i++) {
        int j = NB - 1 - (t * PER4 + i);
        float p = pc[j], n = nc[j];
        if (p > 0.f || n > 0.f) {
            float ec = ((float)j + 0.5f) * (1.f/2048.f);   // bin-center error value
            float U0 = G + N;
            float U1 = U0 + n;
            float r0 = __fdividef(1.f, U0);
            float r1 = __fdividef(1.f, U1);
            // average of pos-first and neg-first within-bin orderings:
            if (p > 0.f) contrib += p * ec * 0.5f * (r0 + r1);
            if (n > 0.f) contrib += n * ec * (G - P - 0.5f*p) * r0 * r1;
        }
        P += p; N += n;
    }
    // warp reduce + block reduce
    #pragma unroll
    for (int o = 16; o; o >>= 1) contrib += __shfl_down_sync(0xffffffffu, contrib, o);
    if (lane == 0) sred[w] = contrib;
    __syncthreads();
    if (t == 0) {
        double s = 0.0;
        for (int k = 0; k < 16; k++) s += (double)sred[k];
        atomicAdd(&g_instl[b], s);
    }
}

// ---------------- pass 5: final reduction (zeroes batch accumulators) ----------------
__global__ void k5(float* __restrict__ out) {
    __shared__ double sh[3][BN];
    int t = threadIdx.x;
    if (t < BN) {
        sh[0][t] = g_instl[t] / (double)g_denom[t];
        sh[1][t] = (double)g_varsum[t] / (double)g_denom[t];
        sh[2][t] = (g_seedl[t] + g_bg[t]) * (1.0/(double)DHW);
        g_instl[t] = 0.0; g_seedl[t] = 0.0; g_bg[t] = 0.0;
    }
    __syncthreads();
    if (t == 0) {
        double li = 0.0, lv = 0.0, ls = 0.0;
        for (int b = 0; b < BN; b++) { li += sh[0][b]; lv += sh[1][b]; ls += sh[2][b]; }
        li /= (double)BN;
        lv = lv * 10.0 / (double)BN;   // W_VAR = 10
        ls /= (double)BN;
        out[0] = (float)li;
        out[1] = (float)lv;
        out[2] = (float)ls;
        out[3] = (float)(li + lv + ls);
    }
}

// ---------------- launch ----------------
extern "C" void kernel_launch(void* const* d_in, const int* in_sizes, int n_in,
                              void* d_out, int out_size) {
    const float* pred = (const float*)d_in[0];
    const int*   inst = (const int*)d_in[1];
    const int*   lab  = (const int*)d_in[2];
    // d_in[3] = center_images (unused), d_in[4] = xyzm (computed analytically)

    cudaFuncSetAttribute(k3, cudaFuncAttributeMaxDynamicSharedMemorySize, 2*NB*4);

    k1<<<dim3(288, BN), 256>>>(pred, inst, lab);
    k2<<<1, 64>>>();
    k3<<<dim3(NPAIR, SLICES, BN), 512, 2*NB*4>>>();
    k4<<<NBI, NT4>>>();
    k5<<<1, 32>>>((float*)d_out);
}

// round 16
// speedup vs baseline: 1.1388x; 1.1388x over previous
#include <cuda_runtime.h>
#include <math.h>

// Problem constants (fixed shapes)
#define DN 32
#define HN 192
#define WN 192
#define DHW (DN*HN*WN)      // 1179648
#define BN 4
#define CN 7
#define NID 16
#define NBI (BN*NID)        // 64
#define NB 4096             // histogram bins over e in [0,2]
#define SLICES 13
#define CH ((DHW + SLICES - 1) / SLICES)   // 90743
#define NPAIR (NID/2)       // 8 id-pairs per batch

typedef unsigned long long ull;

// ---------------- device scratch (static; zero-initialized at load;
// every kernel restores its accumulators to zero after consuming them,
// so each graph replay starts from a clean state) ----------------
__device__ float4 g_se[(size_t)BN*DHW];             // tanh(pred[:3])+xyzm, seed(+id in low mantissa)
__device__ unsigned g_hcnt[NBI][2*NB];              // merged count histograms (2MB)
__device__ double g_acc[NBI][10];                   // cnt, sum_xyz, sum(sig+16), sum sig^2
__device__ double g_bg[BN];
__device__ double g_seedl[BN];
__device__ double g_instl[BN];
__device__ float  g_center[NBI][3];
__device__ float  g_sexp[NBI][3];
__device__ float  g_cnt[NBI];
__device__ float  g_varsum[BN];
__device__ float  g_denom[BN];

// HW tanh (MUFU.TANH, sm_75+); feeds only the binned-distance path
__device__ __forceinline__ float htanh(float x) {
    float y;
    asm("tanh.approx.f32 %0, %1;" : "=f"(y) : "f"(x));
    return y;
}
// guaranteed single-MUFU exp2
__device__ __forceinline__ float hex2(float x) {
    float y;
    asm("ex2.approx.f32 %0, %1;" : "=f"(y) : "f"(x));
    return y;
}

// packed f32x2 helpers (FFMA2/FADD2/FMUL2 — ptxas never auto-fuses these)
#define PACK2(out, lo, hi) \
    asm("mov.b64 %0, {%1, %2};" : "=l"(out) : "r"(__float_as_uint(lo)), "r"(__float_as_uint(hi)))
#define UNPACK2(lo, hi, in) \
    { unsigned _ul, _uh; asm("mov.b64 {%0, %1}, %2;" : "=r"(_ul), "=r"(_uh) : "l"(in)); \
      lo = __uint_as_float(_ul); hi = __uint_as_float(_uh); }
#define ADD2(o,a,b)   asm("add.rn.f32x2 %0, %1, %2;" : "=l"(o) : "l"(a), "l"(b))
#define MUL2(o,a,b)   asm("mul.rn.f32x2 %0, %1, %2;" : "=l"(o) : "l"(a), "l"(b))
#define FMA2(o,a,b,c) asm("fma.rn.f32x2 %0, %1, %2, %3;" : "=l"(o) : "l"(a), "l"(b), "l"(c))

// ---------------- pass 1: preprocess + per-instance accumulators ----------------
// 3 packed u64 words per fg voxel, merged across the 4-voxel quad by id before
// hitting per-warp replica banks:
//  w0: cnt[0:10) | zi[10:24) | yi[24:41) | xi[41:58)          (exact integers)
//  w1: (s0+16)*128 [0:21) | (s1+16)*128 [21:42) | (s2+16)*128 [42:63)
//  w2: s0^2*32 [0:21)     | s1^2*32 [21:42)     | s2^2*32 [42:63)
#define VOXN(i, p0,p1,p2,s0,s1,s2,p6, lbv, xmv, xiv, vi)                         \
    {                                                                            \
        float e0 = htanh(p0) + (xmv);                                            \
        float e1 = htanh(p1) + ym;                                               \
        float e2 = htanh(p2) + zm;                                               \
        float seed = __fdividef(1.f, 1.f + __expf(-(p6)));                       \
        unsigned wb = (__float_as_uint(seed) & ~31u) | (unsigned)ids[i];         \
        o4[vi] = make_float4(e0, e1, e2, __uint_as_float(wb));                   \
        W0[i] = 1ULL | ((ull)zi << 10) | ((ull)yi << 24) | ((ull)(xiv) << 41);   \
        W1[i] = (ull)__float2uint_rn(fmaf(s0,128.f,2048.f))                      \
              | ((ull)__float2uint_rn(fmaf(s1,128.f,2048.f)) << 21)              \
              | ((ull)__float2uint_rn(fmaf(s2,128.f,2048.f)) << 42);             \
        W2[i] = (ull)__float2uint_rn((s0)*(s0)*32.f)                             \
              | ((ull)__float2uint_rn((s1)*(s1)*32.f) << 21)                     \
              | ((ull)__float2uint_rn((s2)*(s2)*32.f) << 42);                    \
        if ((lbv) == 0) bgl += seed * seed;                                      \
    }

__global__ void __launch_bounds__(256) k1(const float* __restrict__ pred,
                                          const int* __restrict__ inst,
                                          const int* __restrict__ lab) {
    __shared__ ull sacc[8][NID*3];   // one replica per warp (3KB)
    __shared__ float swr[8];
    int tid = threadIdx.x;
    for (int i = tid; i < 8*NID*3; i += 256) (&sacc[0][0])[i] = 0ULL;
    __syncthreads();
    ull* my = sacc[tid >> 5];

    int b = blockIdx.y;
    const float4* __restrict__ p4 = (const float4*)(pred + (size_t)b * CN * DHW);
    const int4*   __restrict__ i4 = (const int4*)(inst + (size_t)b * DHW);
    const int4*   __restrict__ l4 = (const int4*)(lab  + (size_t)b * DHW);
    float4* o4 = g_se + (size_t)b * DHW;
    float bgl = 0.f;
    const int Q = DHW / 4;

    for (int q = blockIdx.x * 256 + tid; q < Q; q += gridDim.x * 256) {
        float4 P0 = p4[q],       P1 = p4[Q+q],   P2 = p4[2*Q+q];
        float4 S0 = p4[3*Q+q],   S1 = p4[4*Q+q], S2 = p4[5*Q+q];
        float4 P6 = p4[6*Q+q];
        int4 ID = i4[q];
        int4 LB = l4[q];
        int v = q * 4;
        int x0 = v % WN;
        int r  = v / WN;
        int yi = r % HN, zi = r / HN;
        float ym = (float)yi * (1.f/(HN-1));
        float zm = (float)zi * (1.f/(DN-1));
        float xm = (float)x0 * (1.f/(WN-1));

        int ids[4] = {ID.x, ID.y, ID.z, ID.w};
        ull W0[4], W1[4], W2[4];
        VOXN(0, P0.x, P1.x, P2.x, S0.x, S1.x, S2.x, P6.x, LB.x, xm,              x0,   v+0)
        VOXN(1, P0.y, P1.y, P2.y, S0.y, S1.y, S2.y, P6.y, LB.y, xm + 1.f/(WN-1), x0+1, v+1)
        VOXN(2, P0.z, P1.z, P2.z, S0.z, S1.z, S2.z, P6.z, LB.z, xm + 2.f/(WN-1), x0+2, v+2)
        VOXN(3, P0.w, P1.w, P2.w, S0.w, S1.w, S2.w, P6.w, LB.w, xm + 3.f/(WN-1), x0+3, v+3)

        // merge same-id voxels within the quad, then one atomic triple per id
        #pragma unroll
        for (int i = 0; i < 4; i++) {
            int idv = ids[i];
            if (idv > 0) {
                ull a0 = W0[i], a1 = W1[i], a2 = W2[i];
                #pragma unroll
                for (int j = i + 1; j < 4; j++) {
                    if (ids[j] == idv) { a0 += W0[j]; a1 += W1[j]; a2 += W2[j]; ids[j] = 0; }
                }
                ull* s = &my[(idv-1)*3];
                atomicAdd(&s[0], a0);
                atomicAdd(&s[1], a1);
                atomicAdd(&s[2], a2);
            }
        }
    }
    // warp-reduce bg
    for (int o = 16; o; o >>= 1) bgl += __shfl_down_sync(0xffffffffu, bgl, o);
    if ((tid & 31) == 0) swr[tid >> 5] = bgl;
    __syncthreads();
    if (tid == 0) {
        double s = 0.0;
        for (int i = 0; i < 8; i++) s += (double)swr[i];
        atomicAdd(&g_bg[b], s);
    }
    // decode fields per replica, sum, merge to global (48 threads: id x word)
    if (tid < NID*3) {
        int id = tid / 3, w = tid % 3;
        double* g = g_acc[b*NID + id];
        if (w == 0) {
            ull cnt = 0, sxi = 0, syi = 0, szi = 0;
            #pragma unroll
            for (int rp = 0; rp < 8; rp++) {
                ull v = sacc[rp][id*3];
                cnt += v & 1023ULL;
                szi += (v >> 10) & 0x3FFFULL;
                syi += (v >> 24) & 0x1FFFFULL;
                sxi += (v >> 41);
            }
            if (cnt) {
                atomicAdd(&g[0], (double)cnt);
                atomicAdd(&g[1], (double)sxi * (1.0/(WN-1)));
                atomicAdd(&g[2], (double)syi * (1.0/(HN-1)));
                atomicAdd(&g[3], (double)szi * (1.0/(DN-1)));
            }
        } else {
            ull f0 = 0, f1 = 0, f2 = 0;
            #pragma unroll
            for (int rp = 0; rp < 8; rp++) {
                ull v = sacc[rp][id*3 + w];
                f0 += v & 0x1FFFFFULL;
                f1 += (v >> 21) & 0x1FFFFFULL;
                f2 += (v >> 42);
            }
            if (f0 | f1 | f2) {
                double sc = (w == 1) ? (1.0/128.0) : (1.0/32.0);
                int base = (w == 1) ? 4 : 7;
                atomicAdd(&g[base+0], (double)f0 * sc);
                atomicAdd(&g[base+1], (double)f1 * sc);
                atomicAdd(&g[base+2], (double)f2 * sc);
            }
        }
    }
}

// ---------------- pass 2: per-instance stats (zeroes g_acc after reading) ----------------
// g_acc[4..6] hold sum(sigma+16): subtract 16*cnt here
__global__ void k2() {
    __shared__ float sobj[BN], svar[BN];
    int t = threadIdx.x;            // 0..63  (b*16 + (id-1))
    if (t < BN) { sobj[t] = 0.f; svar[t] = 0.f; }
    __syncthreads();
    int b = t / NID;

    double a[10];
    #pragma unroll
    for (int i = 0; i < 10; i++) { a[i] = g_acc[t][i]; g_acc[t][i] = 0.0; }

    double cnt = a[0];
    bool ex = cnt > 0.0;
    double safe = cnt > 1.0 ? cnt : 1.0;
    double c0 = a[1] / safe, c1 = a[2] / safe, c2 = a[3] / safe;
    double m0 = (a[4] - 16.0*cnt) / safe;
    double m1 = (a[5] - 16.0*cnt) / safe;
    double m2 = (a[6] - 16.0*cnt) / safe;
    double var = 0.0;
    if (ex) {
        var = ((a[7] - cnt*m0*m0) +
               (a[8] - cnt*m1*m1) +
               (a[9] - cnt*m2*m2)) / (3.0 * safe);
    }
    g_center[t][0] = (float)c0; g_center[t][1] = (float)c1; g_center[t][2] = (float)c2;
    g_sexp[t][0] = expf((float)(m0 * 10.0));
    g_sexp[t][1] = expf((float)(m1 * 10.0));
    g_sexp[t][2] = expf((float)(m2 * 10.0));
    g_cnt[t] = ex ? (float)cnt : 0.f;

    atomicAdd(&sobj[b], ex ? 1.f : 0.f);
    atomicAdd(&svar[b], (float)var);
    __syncthreads();
    if (t < BN) {
        g_denom[t]  = sobj[t] > 1.f ? sobj[t] : 1.f;
        g_varsum[t] = svar[t];
    }
}

// ---------------- pass 3: per-(b,idpair,slice) count histograms + seed loss ----------------
// A/B instance math packed into f32x2 (FADD2/FMUL2/FFMA2); scalar tails per instance
#define K3_PAIR(S)                                                               \
    {                                                                            \
        unsigned iv = __float_as_uint(S.w) & 31u;                                \
        ull xx, yy, zz, dx, dy, dz, acc;                                         \
        PACK2(xx, S.x, S.x); PACK2(yy, S.y, S.y); PACK2(zz, S.z, S.z);           \
        ADD2(dx, xx, nc0); ADD2(dy, yy, nc1); ADD2(dz, zz, nc2);                 \
        MUL2(dx, dx, dx); MUL2(dy, dy, dy); MUL2(dz, dz, dz);                    \
        MUL2(acc, dx, ee0); FMA2(acc, dy, ee1, acc); FMA2(acc, dz, ee2, acc);    \
        FMA2(acc, acc, nlg2, tw2);                                               \
        float aA, aB; UNPACK2(aA, aB, acc);                                      \
        float dA = hex2(aA), dB = hex2(aB);                                      \
        bool gtA = (iv == idA);                                                  \
        int ubA = (int)dA; ubA = ubA > NB-1 ? NB-1 : ubA;                        \
        unsigned offA = gtA ? (unsigned)(2*NB - 1 - ubA) : (unsigned)ubA;        \
        atomicAdd(&shA[offA], 1u);                                              \
        if (gtA) { float df = S.w - dA * (1.f/4096.f); sacc += df * df; }        \
        bool gtB = (iv == idB);                                                  \
        int ubB = (int)dB; ubB = ubB > NB-1 ? NB-1 : ubB;                        \
        unsigned offB = gtB ? (unsigned)(2*NB - 1 - ubB) : (unsigned)ubB;        \
        atomicAdd(&shB[offB], 1u);                                              \
        if (gtB) { float df = S.w - dB * (1.f/4096.f); sacc += df * df; }        \
    }

__global__ void __launch_bounds__(512, 3) k3() {
    extern __shared__ unsigned sh[];     // 2 x 2*NB u32 = 64KB
    unsigned* shA = sh;
    unsigned* shB = sh + 2*NB;
    __shared__ float swr[16];

    int b = blockIdx.z, p = blockIdx.x, s = blockIdx.y;
    int biA = b * NID + 2*p, biB = biA + 1;
    unsigned idA = 2*p + 1, idB = 2*p + 2;
    if (g_cnt[biA] == 0.f && g_cnt[biB] == 0.f) return;

    // packed per-pair constants: lane0 = instance A, lane1 = instance B
    ull nc0, nc1, nc2, ee0, ee1, ee2, nlg2, tw2;
    PACK2(nc0, -g_center[biA][0], -g_center[biB][0]);
    PACK2(nc1, -g_center[biA][1], -g_center[biB][1]);
    PACK2(nc2, -g_center[biA][2], -g_center[biB][2]);
    PACK2(ee0, g_sexp[biA][0], g_sexp[biB][0]);
    PACK2(ee1, g_sexp[biA][1], g_sexp[biB][1]);
    PACK2(ee2, g_sexp[biA][2], g_sexp[biB][2]);
    PACK2(nlg2, -1.44269504089f, -1.44269504089f);
    PACK2(tw2, 12.f, 12.f);

    int tid = threadIdx.x;
    for (int i = tid; i < 4*NB; i += 512) sh[i] = 0u;
    __syncthreads();

    const float4* __restrict__ se = g_se + (size_t)b * DHW;
    float sacc = 0.f;
    int v0 = s * CH;
    int vend = v0 + CH; if (vend > DHW) vend = DHW;

    int v = v0 + tid;
    for (; v + 512 < vend; v += 1024) {
        float4 S1 = se[v];
        float4 S2 = se[v + 512];
        K3_PAIR(S1)
        K3_PAIR(S2)
    }
    for (; v < vend; v += 512) {
        float4 S1 = se[v];
        K3_PAIR(S1)
    }

    // warp-reduce seed loss (both instances share batch b)
    for (int o = 16; o; o >>= 1) sacc += __shfl_down_sync(0xffffffffu, sacc, o);
    if ((tid & 31) == 0) swr[tid >> 5] = sacc;
    __syncthreads();
    if (tid == 0) {
        double ssum = 0.0;
        for (int i = 0; i < 16; i++) ssum += (double)swr[i];
        atomicAdd(&g_seedl[b], ssum);
    }
    // sparse merge into single global histogram (RED, no return; deterministic)
    for (int i = tid; i < 2*NB; i += 512) {
        unsigned cA = shA[i];
        unsigned cB = shB[i];
        if (cA) atomicAdd(&g_hcnt[biA][i], cA);
        if (cB) atomicAdd(&g_hcnt[biB][i], cB);
    }
}

// ---------------- pass 4: Lovasz via histogram scan, all-fp32 (counts exact in fp32),
// shuffle-based scan, zeroes g_hcnt after reading ----------------
#define NT4 512
#define PER4 (NB / NT4)   // 8
__global__ void k4() {
    __shared__ float pc[NB], nc[NB];     // counts by ascending bin
    __shared__ float wps[16], wns[16];   // per-warp scan totals
    __shared__ float sred[16];

    int bi = blockIdx.x, b = bi / NID;
    int t = threadIdx.x;
    int lane = t & 31, w = t >> 5;

    // phase 1: coalesced gather of merged counts + restore zeros for next replay
    #pragma unroll
    for (int i = 0; i < PER4; i++) {
        int j = i * NT4 + t;             // ascending bin index, coalesced
        pc[j] = (float)g_hcnt[bi][NB + j];
        nc[j] = (float)g_hcnt[bi][j];
        g_hcnt[bi][NB + j] = 0u;
        g_hcnt[bi][j] = 0u;
    }
    float G = g_cnt[bi];
    if (G == 0.f) return;
    __syncthreads();

    // phase 2: thread-local sums over descending positions [t*PER4, t*PER4+PER4)
    float tp = 0.f, tn = 0.f;
    #pragma unroll
    for (int i = 0; i < PER4; i++) {
        int j = NB - 1 - (t * PER4 + i);
        tp += pc[j]; tn += nc[j];
    }
    // warp-inclusive scan via shuffles
    float ip = tp, inn = tn;
    #pragma unroll
    for (int o = 1; o < 32; o <<= 1) {
        float up = __shfl_up_sync(0xffffffffu, ip, o);
        float un = __shfl_up_sync(0xffffffffu, inn, o);
        if (lane >= o) { ip += up; inn += un; }
    }
    if (lane == 31) { wps[w] = ip; wns[w] = inn; }
    __syncthreads();
    float offP = 0.f, offN = 0.f;
    #pragma unroll
    for (int k = 0; k < 16; k++) {
        float vp = wps[k], vn = wns[k];
        if (k < w) { offP += vp; offN += vn; }
    }
    float P = offP + ip - tp;   // exclusive prefix (exact: integer-valued floats)
    float N = offN + inn - tn;

    float contrib = 0.f;
    #pragma unroll
    for (int i = 0; i < PER4; i++) {
        int j = NB - 1 - (t * PER4 + i);
        float p = pc[j], n = nc[j];
        if (p > 0.f || n > 0.f) {
            float ec = ((float)j + 0.5f) * (1.f/2048.f);   // bin-center error value
            float U0 = G + N;
            float U1 = U0 + n;
            float r0 = __fdividef(1.f, U0);
            float r1 = __fdividef(1.f, U1);
            // average of pos-first and neg-first within-bin orderings:
            if (p > 0.f) contrib += p * ec * 0.5f * (r0 + r1);
            if (n > 0.f) contrib += n * ec * (G - P - 0.5f*p) * r0 * r1;
        }
        P += p; N += n;
    }
    // warp reduce + block reduce
    #pragma unroll
    for (int o = 16; o; o >>= 1) contrib += __shfl_down_sync(0xffffffffu, contrib, o);
    if (lane == 0) sred[w] = contrib;
    __syncthreads();
    if (t == 0) {
        double s = 0.0;
        for (int k = 0; k < 16; k++) s += (double)sred[k];
        atomicAdd(&g_instl[b], s);
    }
}

// ---------------- pass 5: final reduction (zeroes batch accumulators) ----------------
__global__ void k5(float* __restrict__ out) {
    __shared__ double sh[3][BN];
    int t = threadIdx.x;
    if (t < BN) {
        sh[0][t] = g_instl[t] / (double)g_denom[t];
        sh[1][t] = (double)g_varsum[t] / (double)g_denom[t];
        sh[2][t] = (g_seedl[t] + g_bg[t]) * (1.0/(double)DHW);
        g_instl[t] = 0.0; g_seedl[t] = 0.0; g_bg[t] = 0.0;
    }
    __syncthreads();
    if (t == 0) {
        double li = 0.0, lv = 0.0, ls = 0.0;
        for (int b = 0; b < BN; b++) { li += sh[0][b]; lv += sh[1][b]; ls += sh[2][b]; }
        li /= (double)BN;
        lv = lv * 10.0 / (double)BN;   // W_VAR = 10
        ls /= (double)BN;
        out[0] = (float)li;
        out[1] = (float)lv;
        out[2] = (float)ls;
        out[3] = (float)(li + lv + ls);
    }
}

// ---------------- launch ----------------
extern "C" void kernel_launch(void* const* d_in, const int* in_sizes, int n_in,
                              void* d_out, int out_size) {
    const float* pred = (const float*)d_in[0];
    const int*   inst = (const int*)d_in[1];
    const int*   lab  = (const int*)d_in[2];
    // d_in[3] = center_images (unused), d_in[4] = xyzm (computed analytically)

    cudaFuncSetAttribute(k3, cudaFuncAttributeMaxDynamicSharedMemorySize, 4*NB*4);

    k1<<<dim3(288, BN), 256>>>(pred, inst, lab);
    k2<<<1, 64>>>();
    k3<<<dim3(NPAIR, SLICES, BN), 512, 4*NB*4>>>();
    k4<<<NBI, NT4>>>();
    k5<<<1, 32>>>((float*)d_out);
}

// round 17
// speedup vs baseline: 1.2579x; 1.1046x over previous
#include <cuda_runtime.h>
#include <math.h>

// Problem constants (fixed shapes)
#define DN 32
#define HN 192
#define WN 192
#define DHW (DN*HN*WN)      // 1179648
#define BN 4
#define CN 7
#define NID 16
#define NBI (BN*NID)        // 64
#define NB 4096             // histogram bins over e in [0,2]
#define SLICES 9
#define CH ((DHW + SLICES - 1) / SLICES)   // 131072
#define NPAIR (NID/2)       // 8 id-pairs per batch

typedef unsigned long long ull;

// ---------------- device scratch (static; zero-initialized at load;
// every kernel restores its accumulators to zero after consuming them,
// so each graph replay starts from a clean state) ----------------
__device__ float4 g_se[(size_t)BN*DHW];             // tanh(pred[:3])+xyzm, seed(+id in low mantissa)
__device__ unsigned g_hcnt[NBI][2*NB];              // merged count histograms (2MB)
__device__ double g_acc[NBI][10];                   // cnt, sum_xyz, sum(sig+16), sum sig^2
__device__ double g_bg[BN];
__device__ double g_seedl[BN];
__device__ double g_instl[BN];
__device__ float  g_center[NBI][3];
__device__ float  g_sexp[NBI][3];
__device__ float  g_cnt[NBI];
__device__ float  g_varsum[BN];
__device__ float  g_denom[BN];

// HW tanh (MUFU.TANH, sm_75+); feeds only the binned-distance path
__device__ __forceinline__ float htanh(float x) {
    float y;
    asm("tanh.approx.f32 %0, %1;" : "=f"(y) : "f"(x));
    return y;
}
// guaranteed single-MUFU exp2
__device__ __forceinline__ float hex2(float x) {
    float y;
    asm("ex2.approx.f32 %0, %1;" : "=f"(y) : "f"(x));
    return y;
}

// packed f32x2 helpers (FFMA2/FADD2/FMUL2 — ptxas never auto-fuses these)
#define PACK2(out, lo, hi) \
    asm("mov.b64 %0, {%1, %2};" : "=l"(out) : "r"(__float_as_uint(lo)), "r"(__float_as_uint(hi)))
#define UNPACK2(lo, hi, in) \
    { unsigned _ul, _uh; asm("mov.b64 {%0, %1}, %2;" : "=r"(_ul), "=r"(_uh) : "l"(in)); \
      lo = __uint_as_float(_ul); hi = __uint_as_float(_uh); }
#define ADD2(o,a,b)   asm("add.rn.f32x2 %0, %1, %2;" : "=l"(o) : "l"(a), "l"(b))
#define MUL2(o,a,b)   asm("mul.rn.f32x2 %0, %1, %2;" : "=l"(o) : "l"(a), "l"(b))
#define FMA2(o,a,b,c) asm("fma.rn.f32x2 %0, %1, %2, %3;" : "=l"(o) : "l"(a), "l"(b), "l"(c))

// ---------------- pass 1: preprocess + per-instance accumulators ----------------
// 3 packed u64 words per fg voxel, merged across the 4-voxel quad by id before
// hitting per-HALF-WARP replica banks (16 replicas halve same-address degree):
//  w0: cnt[0:10) | zi[10:24) | yi[24:41) | xi[41:58)          (exact integers)
//  w1: (s0+16)*128 [0:21) | (s1+16)*128 [21:42) | (s2+16)*128 [42:63)
//  w2: s0^2*32 [0:21)     | s1^2*32 [21:42)     | s2^2*32 [42:63)
#define VOXN(i, p0,p1,p2,s0,s1,s2,p6, lbv, xmv, xiv, vi)                         \
    {                                                                            \
        float e0 = htanh(p0) + (xmv);                                            \
        float e1 = htanh(p1) + ym;                                               \
        float e2 = htanh(p2) + zm;                                               \
        float seed = __fdividef(1.f, 1.f + __expf(-(p6)));                       \
        unsigned wb = (__float_as_uint(seed) & ~31u) | (unsigned)ids[i];         \
        o4[vi] = make_float4(e0, e1, e2, __uint_as_float(wb));                   \
        W0[i] = 1ULL | ((ull)zi << 10) | ((ull)yi << 24) | ((ull)(xiv) << 41);   \
        W1[i] = (ull)__float2uint_rn(fmaf(s0,128.f,2048.f))                      \
              | ((ull)__float2uint_rn(fmaf(s1,128.f,2048.f)) << 21)              \
              | ((ull)__float2uint_rn(fmaf(s2,128.f,2048.f)) << 42);             \
        W2[i] = (ull)__float2uint_rn((s0)*(s0)*32.f)                             \
              | ((ull)__float2uint_rn((s1)*(s1)*32.f) << 21)                     \
              | ((ull)__float2uint_rn((s2)*(s2)*32.f) << 42);                    \
        if ((lbv) == 0) bgl += seed * seed;                                      \
    }

__global__ void __launch_bounds__(256) k1(const float* __restrict__ pred,
                                          const int* __restrict__ inst,
                                          const int* __restrict__ lab) {
    __shared__ ull sacc[16][NID*3];   // one replica per half-warp (6KB)
    __shared__ float swr[8];
    int tid = threadIdx.x;
    for (int i = tid; i < 16*NID*3; i += 256) (&sacc[0][0])[i] = 0ULL;
    __syncthreads();
    ull* my = sacc[tid >> 4];   // half-warp replica

    int b = blockIdx.y;
    const float4* __restrict__ p4 = (const float4*)(pred + (size_t)b * CN * DHW);
    const int4*   __restrict__ i4 = (const int4*)(inst + (size_t)b * DHW);
    const int4*   __restrict__ l4 = (const int4*)(lab  + (size_t)b * DHW);
    float4* o4 = g_se + (size_t)b * DHW;
    float bgl = 0.f;
    const int Q = DHW / 4;

    for (int q = blockIdx.x * 256 + tid; q < Q; q += gridDim.x * 256) {
        float4 P0 = p4[q],       P1 = p4[Q+q],   P2 = p4[2*Q+q];
        float4 S0 = p4[3*Q+q],   S1 = p4[4*Q+q], S2 = p4[5*Q+q];
        float4 P6 = p4[6*Q+q];
        int4 ID = i4[q];
        int4 LB = l4[q];
        int v = q * 4;
        int x0 = v % WN;
        int r  = v / WN;
        int yi = r % HN, zi = r / HN;
        float ym = (float)yi * (1.f/(HN-1));
        float zm = (float)zi * (1.f/(DN-1));
        float xm = (float)x0 * (1.f/(WN-1));

        int ids[4] = {ID.x, ID.y, ID.z, ID.w};
        ull W0[4], W1[4], W2[4];
        VOXN(0, P0.x, P1.x, P2.x, S0.x, S1.x, S2.x, P6.x, LB.x, xm,              x0,   v+0)
        VOXN(1, P0.y, P1.y, P2.y, S0.y, S1.y, S2.y, P6.y, LB.y, xm + 1.f/(WN-1), x0+1, v+1)
        VOXN(2, P0.z, P1.z, P2.z, S0.z, S1.z, S2.z, P6.z, LB.z, xm + 2.f/(WN-1), x0+2, v+2)
        VOXN(3, P0.w, P1.w, P2.w, S0.w, S1.w, S2.w, P6.w, LB.w, xm + 3.f/(WN-1), x0+3, v+3)

        // merge same-id voxels within the quad, then one atomic triple per id
        #pragma unroll
        for (int i = 0; i < 4; i++) {
            int idv = ids[i];
            if (idv > 0) {
                ull a0 = W0[i], a1 = W1[i], a2 = W2[i];
                #pragma unroll
                for (int j = i + 1; j < 4; j++) {
                    if (ids[j] == idv) { a0 += W0[j]; a1 += W1[j]; a2 += W2[j]; ids[j] = 0; }
                }
                ull* s = &my[(idv-1)*3];
                atomicAdd(&s[0], a0);
                atomicAdd(&s[1], a1);
                atomicAdd(&s[2], a2);
            }
        }
    }
    // warp-reduce bg
    for (int o = 16; o; o >>= 1) bgl += __shfl_down_sync(0xffffffffu, bgl, o);
    if ((tid & 31) == 0) swr[tid >> 5] = bgl;
    __syncthreads();
    if (tid == 0) {
        double s = 0.0;
        for (int i = 0; i < 8; i++) s += (double)swr[i];
        atomicAdd(&g_bg[b], s);
    }
    // decode fields per replica, sum, merge to global (48 threads: id x word)
    if (tid < NID*3) {
        int id = tid / 3, w = tid % 3;
        double* g = g_acc[b*NID + id];
        if (w == 0) {
            ull cnt = 0, sxi = 0, syi = 0, szi = 0;
            #pragma unroll
            for (int rp = 0; rp < 16; rp++) {
                ull v = sacc[rp][id*3];
                cnt += v & 1023ULL;
                szi += (v >> 10) & 0x3FFFULL;
                syi += (v >> 24) & 0x1FFFFULL;
                sxi += (v >> 41);
            }
            if (cnt) {
                atomicAdd(&g[0], (double)cnt);
                atomicAdd(&g[1], (double)sxi * (1.0/(WN-1)));
                atomicAdd(&g[2], (double)syi * (1.0/(HN-1)));
                atomicAdd(&g[3], (double)szi * (1.0/(DN-1)));
            }
        } else {
            ull f0 = 0, f1 = 0, f2 = 0;
            #pragma unroll
            for (int rp = 0; rp < 16; rp++) {
                ull v = sacc[rp][id*3 + w];
                f0 += v & 0x1FFFFFULL;
                f1 += (v >> 21) & 0x1FFFFFULL;
                f2 += (v >> 42);
            }
            if (f0 | f1 | f2) {
                double sc = (w == 1) ? (1.0/128.0) : (1.0/32.0);
                int base = (w == 1) ? 4 : 7;
                atomicAdd(&g[base+0], (double)f0 * sc);
                atomicAdd(&g[base+1], (double)f1 * sc);
                atomicAdd(&g[base+2], (double)f2 * sc);
            }
        }
    }
}

// ---------------- pass 2: per-instance stats (zeroes g_acc after reading) ----------------
// g_acc[4..6] hold sum(sigma+16): subtract 16*cnt here
__global__ void k2() {
    __shared__ float sobj[BN], svar[BN];
    int t = threadIdx.x;            // 0..63  (b*16 + (id-1))
    if (t < BN) { sobj[t] = 0.f; svar[t] = 0.f; }
    __syncthreads();
    int b = t / NID;

    double a[10];
    #pragma unroll
    for (int i = 0; i < 10; i++) { a[i] = g_acc[t][i]; g_acc[t][i] = 0.0; }

    double cnt = a[0];
    bool ex = cnt > 0.0;
    double safe = cnt > 1.0 ? cnt : 1.0;
    double c0 = a[1] / safe, c1 = a[2] / safe, c2 = a[3] / safe;
    double m0 = (a[4] - 16.0*cnt) / safe;
    double m1 = (a[5] - 16.0*cnt) / safe;
    double m2 = (a[6] - 16.0*cnt) / safe;
    double var = 0.0;
    if (ex) {
        var = ((a[7] - cnt*m0*m0) +
               (a[8] - cnt*m1*m1) +
               (a[9] - cnt*m2*m2)) / (3.0 * safe);
    }
    g_center[t][0] = (float)c0; g_center[t][1] = (float)c1; g_center[t][2] = (float)c2;
    g_sexp[t][0] = expf((float)(m0 * 10.0));
    g_sexp[t][1] = expf((float)(m1 * 10.0));
    g_sexp[t][2] = expf((float)(m2 * 10.0));
    g_cnt[t] = ex ? (float)cnt : 0.f;

    atomicAdd(&sobj[b], ex ? 1.f : 0.f);
    atomicAdd(&svar[b], (float)var);
    __syncthreads();
    if (t < BN) {
        g_denom[t]  = sobj[t] > 1.f ? sobj[t] : 1.f;
        g_varsum[t] = svar[t];
    }
}

// ---------------- pass 3: per-(b,idpair,slice) count histograms + seed loss ----------------
// A/B instance math packed into f32x2 (FADD2/FMUL2/FFMA2); scalar tails per instance
#define K3_PAIR(S)                                                               \
    {                                                                            \
        unsigned iv = __float_as_uint(S.w) & 31u;                                \
        ull xx, yy, zz, dx, dy, dz, acc;                                         \
        PACK2(xx, S.x, S.x); PACK2(yy, S.y, S.y); PACK2(zz, S.z, S.z);           \
        ADD2(dx, xx, nc0); ADD2(dy, yy, nc1); ADD2(dz, zz, nc2);                 \
        MUL2(dx, dx, dx); MUL2(dy, dy, dy); MUL2(dz, dz, dz);                    \
        MUL2(acc, dx, ee0); FMA2(acc, dy, ee1, acc); FMA2(acc, dz, ee2, acc);    \
        FMA2(acc, acc, nlg2, tw2);                                               \
        float aA, aB; UNPACK2(aA, aB, acc);                                      \
        float dA = hex2(aA), dB = hex2(aB);                                      \
        bool gtA = (iv == idA);                                                  \
        int ubA = (int)dA; ubA = ubA > NB-1 ? NB-1 : ubA;                        \
        unsigned offA = gtA ? (unsigned)(2*NB - 1 - ubA) : (unsigned)ubA;        \
        atomicAdd(&shA[offA], 1u);                                              \
        if (gtA) { float df = S.w - dA * (1.f/4096.f); sacc += df * df; }        \
        bool gtB = (iv == idB);                                                  \
        int ubB = (int)dB; ubB = ubB > NB-1 ? NB-1 : ubB;                        \
        unsigned offB = gtB ? (unsigned)(2*NB - 1 - ubB) : (unsigned)ubB;        \
        atomicAdd(&shB[offB], 1u);                                              \
        if (gtB) { float df = S.w - dB * (1.f/4096.f); sacc += df * df; }        \
    }

__global__ void __launch_bounds__(1024, 2) k3() {
    extern __shared__ unsigned sh[];     // 2 x 2*NB u32 = 64KB
    unsigned* shA = sh;
    unsigned* shB = sh + 2*NB;
    __shared__ float swr[32];

    int b = blockIdx.z, p = blockIdx.x, s = blockIdx.y;
    int biA = b * NID + 2*p, biB = biA + 1;
    unsigned idA = 2*p + 1, idB = 2*p + 2;
    if (g_cnt[biA] == 0.f && g_cnt[biB] == 0.f) return;

    // packed per-pair constants: lane0 = instance A, lane1 = instance B
    ull nc0, nc1, nc2, ee0, ee1, ee2, nlg2, tw2;
    PACK2(nc0, -g_center[biA][0], -g_center[biB][0]);
    PACK2(nc1, -g_center[biA][1], -g_center[biB][1]);
    PACK2(nc2, -g_center[biA][2], -g_center[biB][2]);
    PACK2(ee0, g_sexp[biA][0], g_sexp[biB][0]);
    PACK2(ee1, g_sexp[biA][1], g_sexp[biB][1]);
    PACK2(ee2, g_sexp[biA][2], g_sexp[biB][2]);
    PACK2(nlg2, -1.44269504089f, -1.44269504089f);
    PACK2(tw2, 12.f, 12.f);

    int tid = threadIdx.x;
    for (int i = tid; i < 4*NB; i += 1024) sh[i] = 0u;
    __syncthreads();

    const float4* __restrict__ se = g_se + (size_t)b * DHW;
    float sacc = 0.f;
    int v0 = s * CH;
    int vend = v0 + CH; if (vend > DHW) vend = DHW;

    int v = v0 + tid;
    for (; v + 1024 < vend; v += 2048) {
        float4 S1 = se[v];
        float4 S2 = se[v + 1024];
        K3_PAIR(S1)
        K3_PAIR(S2)
    }
    for (; v < vend; v += 1024) {
        float4 S1 = se[v];
        K3_PAIR(S1)
    }

    // warp-reduce seed loss (both instances share batch b)
    for (int o = 16; o; o >>= 1) sacc += __shfl_down_sync(0xffffffffu, sacc, o);
    if ((tid & 31) == 0) swr[tid >> 5] = sacc;
    __syncthreads();
    if (tid == 0) {
        double ssum = 0.0;
        for (int i = 0; i < 32; i++) ssum += (double)swr[i];
        atomicAdd(&g_seedl[b], ssum);
    }
    // sparse merge into single global histogram (RED, no return; deterministic)
    for (int i = tid; i < 2*NB; i += 1024) {
        unsigned cA = shA[i];
        unsigned cB = shB[i];
        if (cA) atomicAdd(&g_hcnt[biA][i], cA);
        if (cB) atomicAdd(&g_hcnt[biB][i], cB);
    }
}

// ---------------- pass 4: Lovasz via histogram scan, all-fp32 (counts exact in fp32),
// shuffle-based scan, zeroes g_hcnt after reading ----------------
#define NT4 512
#define PER4 (NB / NT4)   // 8
__global__ void k4() {
    __shared__ float pc[NB], nc[NB];     // counts by ascending bin
    __shared__ float wps[16], wns[16];   // per-warp scan totals
    __shared__ float sred[16];

    int bi = blockIdx.x, b = bi / NID;
    int t = threadIdx.x;
    int lane = t & 31, w = t >> 5;

    // phase 1: coalesced gather of merged counts + restore zeros for next replay
    #pragma unroll
    for (int i = 0; i < PER4; i++) {
        int j = i * NT4 + t;             // ascending bin index, coalesced
        pc[j] = (float)g_hcnt[bi][NB + j];
        nc[j] = (float)g_hcnt[bi][j];
        g_hcnt[bi][NB + j] = 0u;
        g_hcnt[bi][j] = 0u;
    }
    float G = g_cnt[bi];
    if (G == 0.f) return;
    __syncthreads();

    // phase 2: thread-local sums over descending positions [t*PER4, t*PER4+PER4)
    float tp = 0.f, tn = 0.f;
    #pragma unroll
    for (int i = 0; i < PER4; i++) {
        int j = NB - 1 - (t * PER4 + i);
        tp += pc[j]; tn += nc[j];
    }
    // warp-inclusive scan via shuffles
    float ip = tp, inn = tn;
    #pragma unroll
    for (int o = 1; o < 32; o <<= 1) {
        float up = __shfl_up_sync(0xffffffffu, ip, o);
        float un = __shfl_up_sync(0xffffffffu, inn, o);
        if (lane >= o) { ip += up; inn += un; }
    }
    if (lane == 31) { wps[w] = ip; wns[w] = inn; }
    __syncthreads();
    float offP = 0.f, offN = 0.f;
    #pragma unroll
    for (int k = 0; k < 16; k++) {
        float vp = wps[k], vn = wns[k];
        if (k < w) { offP += vp; offN += vn; }
    }
    float P = offP + ip - tp;   // exclusive prefix (exact: integer-valued floats)
    float N = offN + inn - tn;

    float contrib = 0.f;
    #pragma unroll
    for (int i = 0; i < PER4; i++) {
        int j = NB - 1 - (t * PER4 + i);
        float p = pc[j], n = nc[j];
        if (p > 0.f || n > 0.f) {
            float ec = ((float)j + 0.5f) * (1.f/2048.f);   // bin-center error value
            float U0 = G + N;
            float U1 = U0 + n;
            float r0 = __fdividef(1.f, U0);
            float r1 = __fdividef(1.f, U1);
            // average of pos-first and neg-first within-bin orderings:
            if (p > 0.f) contrib += p * ec * 0.5f * (r0 + r1);
            if (n > 0.f) contrib += n * ec * (G - P - 0.5f*p) * r0 * r1;
        }
        P += p; N += n;
    }
    // warp reduce + block reduce
    #pragma unroll
    for (int o = 16; o; o >>= 1) contrib += __shfl_down_sync(0xffffffffu, contrib, o);
    if (lane == 0) sred[w] = contrib;
    __syncthreads();
    if (t == 0) {
        double s = 0.0;
        for (int k = 0; k < 16; k++) s += (double)sred[k];
        atomicAdd(&g_instl[b], s);
    }
}

// ---------------- pass 5: final reduction (zeroes batch accumulators) ----------------
__global__ void k5(float* __restrict__ out) {
    __shared__ double sh[3][BN];
    int t = threadIdx.x;
    if (t < BN) {
        sh[0][t] = g_instl[t] / (double)g_denom[t];
        sh[1][t] = (double)g_varsum[t] / (double)g_denom[t];
        sh[2][t] = (g_seedl[t] + g_bg[t]) * (1.0/(double)DHW);
        g_instl[t] = 0.0; g_seedl[t] = 0.0; g_bg[t] = 0.0;
    }
    __syncthreads();
    if (t == 0) {
        double li = 0.0, lv = 0.0, ls = 0.0;
        for (int b = 0; b < BN; b++) { li += sh[0][b]; lv += sh[1][b]; ls += sh[2][b]; }
        li /= (double)BN;
        lv = lv * 10.0 / (double)BN;   // W_VAR = 10
        ls /= (double)BN;
        out[0] = (float)li;
        out[1] = (float)lv;
        out[2] = (float)ls;
        out[3] = (float)(li + lv + ls);
    }
}

// ---------------- launch ----------------
extern "C" void kernel_launch(void* const* d_in, const int* in_sizes, int n_in,
                              void* d_out, int out_size) {
    const float* pred = (const float*)d_in[0];
    const int*   inst = (const int*)d_in[1];
    const int*   lab  = (const int*)d_in[2];
    // d_in[3] = center_images (unused), d_in[4] = xyzm (computed analytically)

    cudaFuncSetAttribute(k3, cudaFuncAttributeMaxDynamicSharedMemorySize, 4*NB*4);

    k1<<<dim3(288, BN), 256>>>(pred, inst, lab);
    k2<<<1, 64>>>();
    k3<<<dim3(NPAIR, SLICES, BN), 1024, 4*NB*4>>>();
    k4<<<NBI, NT4>>>();
    k5<<<1, 32>>>((float*)d_out);
}